// round 9
// baseline (speedup 1.0000x reference)
#include <cuda_runtime.h>
#include <cuda_fp16.h>

#define H 64
#define IN_DIM 16
#define NMAX 50048
#define EPADMAX 1200000

// scratch (allocation-free rule: __device__ globals)
__device__ float    g_dinv[NMAX];
__device__ float    g_h[NMAX * H];
__device__ __half   g_th[NMAX * H];     // t stored fp16 (messages)
__device__ int      g_cnt[NMAX];        // in-degree counts (excl self-loop)
__device__ int      g_rowptr[NMAX + 1];
__device__ int      g_wr[NMAX];         // write cursors for CSR fill
__device__ __align__(16) unsigned g_se[EPADMAX];  // packed {norm:f16 <<16 | src:u16}; rows padded to 8
__device__ int      g_bsum[64];         // scan block sums

// ---------------- CSR build ----------------

__global__ void count_kernel(const int* __restrict__ col, int E) {
    int e = blockIdx.x * blockDim.x + threadIdx.x;
    if (e < E) atomicAdd(&g_cnt[col[e]], 1);
}

// block-level exclusive scan of PADDED counts (1024 elems/block)
__global__ void scanA(int N) {
    __shared__ int s[1024];
    int tid = threadIdx.x;
    int i = blockIdx.x * 1024 + tid;
    int v = (i < N) ? ((g_cnt[i] + 7) & ~7) : 0;
    s[tid] = v;
    __syncthreads();
    for (int o = 1; o < 1024; o <<= 1) {
        int t = (tid >= o) ? s[tid - o] : 0;
        __syncthreads();
        s[tid] += t;
        __syncthreads();
    }
    if (i < N) g_rowptr[i] = s[tid] - v;  // exclusive within block
    if (tid == 1023) g_bsum[blockIdx.x] = s[1023];
}

// finalize rowptr: each 256-block computes its 1024-segment's bsum prefix in-warp
__global__ void scanC(int N) {
    __shared__ int sbase;
    int i = blockIdx.x * 256 + threadIdx.x;
    int seg = (blockIdx.x * 256) >> 10;  // all threads of block share one segment
    if (threadIdx.x < 32) {
        int l = threadIdx.x;
        int v = ((l < seg) ? g_bsum[l] : 0) + ((l + 32 < seg) ? g_bsum[l + 32] : 0);
#pragma unroll
        for (int o = 16; o; o >>= 1) v += __shfl_xor_sync(0xFFFFFFFFu, v, o);
        if (l == 0) sbase = v;
    }
    __syncthreads();
    if (i < N) {
        int rp = g_rowptr[i] + sbase;
        g_rowptr[i] = rp;
        g_wr[i] = rp;
        g_dinv[i] = rsqrtf((float)g_cnt[i] + 1.0f);  // +1 self-loop
        if (i == N - 1) g_rowptr[N] = rp + ((g_cnt[i] + 7) & ~7);
    }
}

__global__ void build_kernel(const int* __restrict__ ei, int E) {
    int e = blockIdx.x * blockDim.x + threadIdx.x;
    if (e >= E) return;
    int r = ei[e], c = ei[E + e];
    int slot = atomicAdd(&g_wr[c], 1);
    __half nh = __float2half_rn(g_dinv[r] * g_dinv[c]);
    g_se[slot] = ((unsigned)__half_as_ushort(nh) << 16) | (unsigned)r;  // src < 65536
}

// ---------------- input GEMM: h = relu(x @ W_in + b_in) ----------------

__global__ void in_gemm(const float* __restrict__ x, const float* __restrict__ Win,
                        const float* __restrict__ bin, int N) {
    __shared__ float sW[IN_DIM * H];
    __shared__ float sx[32][IN_DIM];
    int tid = threadIdx.x;
    for (int i = tid; i < IN_DIM * H; i += 256) sW[i] = Win[i];
    int base = blockIdx.x * 32;
    for (int i = tid; i < 32 * IN_DIM; i += 256) {
        int n = i / IN_DIM, k = i % IN_DIM;
        int node = base + n;
        sx[n][k] = (node < N) ? x[node * IN_DIM + k] : 0.0f;
    }
    __syncthreads();
    int j = tid & 63, sub = tid >> 6;
    float bj = bin[j];
    for (int n = sub; n < 32; n += 4) {
        int node = base + n;
        if (node >= N) break;
        float acc = bj;
#pragma unroll
        for (int k = 0; k < IN_DIM; k++) acc += sx[n][k] * sW[k * H + j];
        g_h[node * H + j] = fmaxf(acc, 0.0f);
    }
}

// ---------------- per-layer transform: t = h @ W  (fp32 math, fp16 store) ----------------

__global__ void __launch_bounds__(256) conv_gemm(const float* __restrict__ W, int N) {
    __shared__ __align__(16) float sh[64][H];  // 16 KB
    int tid = threadIdx.x;
    int j = tid & 63, sub = tid >> 6;
    int base = blockIdx.x * 64;
    int nn = N - base;
    if (nn > 64) nn = 64;
    if (nn <= 0) return;

    float w[H];
#pragma unroll
    for (int k = 0; k < H; k++) w[k] = W[k * H + j];  // coalesced across j

    const float4* hsrc = (const float4*)&g_h[base * H];
    float4* sdst = (float4*)sh;
    int nvec = nn * (H / 4);
    for (int i = tid; i < nvec; i += 256) sdst[i] = hsrc[i];
    __syncthreads();

    for (int n = sub; n < nn; n += 4) {
        const float4* sp = (const float4*)&sh[n][0];
        float acc = 0.0f;
#pragma unroll
        for (int q = 0; q < 16; q++) {
            float4 s = sp[q];
            acc += s.x * w[4 * q] + s.y * w[4 * q + 1] + s.z * w[4 * q + 2] + s.w * w[4 * q + 3];
        }
        g_th[(base + n) * H + j] = __float2half_rn(acc);  // 2B coalesced store
    }
}

// ---------------- fused gather + bias + self-loop + LN + ReLU + residual (+ head) ----------------
// one warp per node; lane owns features (2*lane, 2*lane+1); messages read as half2.
// rows padded to multiple of 8 (zero-norm sentinels) -> pure unroll-8, no tail;
// metadata read as 2x LDG.128 (rows 32B-aligned).

__device__ __forceinline__ void unpack_se(unsigned m, int& src, float& nm) {
    src = (int)(m & 0xFFFFu);
    nm = __half2float(__ushort_as_half((unsigned short)(m >> 16)));
}

__global__ void gather_ln(const float* __restrict__ b,
                          const float* __restrict__ gamma, const float* __restrict__ beta,
                          const float* __restrict__ Wout, const float* __restrict__ bout,
                          float* __restrict__ out, int N, int last) {
    int node = (blockIdx.x * blockDim.x + threadIdx.x) >> 5;
    int lane = threadIdx.x & 31;
    if (node >= N) return;

    const __half2* t2 = (const __half2*)g_th;
    float d = g_dinv[node];
    float2 b2 = ((const float2*)b)[lane];
    float2 tn = __half22float2(t2[node * 32 + lane]);
    float accx = b2.x + tn.x * d * d;   // bias + self-loop message
    float accy = b2.y + tn.y * d * d;

    int s = g_rowptr[node], e = g_rowptr[node + 1];
    for (int j = s; j < e; j += 8) {
        const uint4* mp = (const uint4*)&g_se[j];
        uint4 ma = mp[0], mb = mp[1];
        int r0, r1, r2, r3, r4, r5, r6, r7;
        float n0, n1, n2, n3, n4, n5, n6, n7;
        unpack_se(ma.x, r0, n0); unpack_se(ma.y, r1, n1);
        unpack_se(ma.z, r2, n2); unpack_se(ma.w, r3, n3);
        unpack_se(mb.x, r4, n4); unpack_se(mb.y, r5, n5);
        unpack_se(mb.z, r6, n6); unpack_se(mb.w, r7, n7);
        float2 v0 = __half22float2(t2[r0 * 32 + lane]);
        float2 v1 = __half22float2(t2[r1 * 32 + lane]);
        float2 v2 = __half22float2(t2[r2 * 32 + lane]);
        float2 v3 = __half22float2(t2[r3 * 32 + lane]);
        float2 v4 = __half22float2(t2[r4 * 32 + lane]);
        float2 v5 = __half22float2(t2[r5 * 32 + lane]);
        float2 v6 = __half22float2(t2[r6 * 32 + lane]);
        float2 v7 = __half22float2(t2[r7 * 32 + lane]);
        accx += v0.x * n0 + v1.x * n1 + v2.x * n2 + v3.x * n3
              + v4.x * n4 + v5.x * n5 + v6.x * n6 + v7.x * n7;
        accy += v0.y * n0 + v1.y * n1 + v2.y * n2 + v3.y * n3
              + v4.y * n4 + v5.y * n5 + v6.y * n6 + v7.y * n7;
    }

    // layernorm over 64 features
    float ssum = accx + accy;
#pragma unroll
    for (int o = 16; o; o >>= 1) ssum += __shfl_xor_sync(0xFFFFFFFFu, ssum, o);
    float mu = ssum * (1.0f / 64.0f);
    float dx = accx - mu, dy = accy - mu;
    float var = dx * dx + dy * dy;
#pragma unroll
    for (int o = 16; o; o >>= 1) var += __shfl_xor_sync(0xFFFFFFFFu, var, o);
    float inv = rsqrtf(var * (1.0f / 64.0f) + 1e-5f);

    float2 g2 = ((const float2*)gamma)[lane];
    float2 be2 = ((const float2*)beta)[lane];
    float2* hp = (float2*)&g_h[node * H];
    float2 hres = hp[lane];
    float r0 = fmaxf(dx * inv * g2.x + be2.x, 0.0f) + hres.x;
    float r1 = fmaxf(dy * inv * g2.y + be2.y, 0.0f) + hres.y;
    hp[lane] = make_float2(r0, r1);

    if (last) {
        float2 w2 = ((const float2*)Wout)[lane];
        float o_ = r0 * w2.x + r1 * w2.y;
#pragma unroll
        for (int o = 16; o; o >>= 1) o_ += __shfl_xor_sync(0xFFFFFFFFu, o_, o);
        if (lane == 0) out[node] = o_ + bout[0];
    }
}

// ---------------- launch ----------------

extern "C" void kernel_launch(void* const* d_in, const int* in_sizes, int n_in,
                              void* d_out, int out_size) {
    const float* x      = (const float*)d_in[0];
    const int*   ei     = (const int*)d_in[1];
    const float* W_in   = (const float*)d_in[2];
    const float* b_in   = (const float*)d_in[3];
    const float* W_conv = (const float*)d_in[4];
    const float* b_conv = (const float*)d_in[5];
    const float* gamma  = (const float*)d_in[6];
    const float* beta   = (const float*)d_in[7];
    const float* W_out  = (const float*)d_in[8];
    const float* b_out  = (const float*)d_in[9];
    float* out = (float*)d_out;

    int N = in_sizes[0] / IN_DIM;
    int E = in_sizes[1] / 2;
    int nblk_scan = (N + 1023) / 1024;

    // fork a side stream off the capturing (legacy default) stream:
    // CSR chain on stream 0, in_gemm + conv0 on s2, join before gather l0.
    cudaStream_t s2;
    cudaStreamCreate(&s2);
    cudaEvent_t e0, e1;
    cudaEventCreate(&e0);
    cudaEventCreate(&e1);
    cudaEventRecord(e0, 0);
    cudaStreamWaitEvent(s2, e0, 0);

    // branch B (independent of CSR): input GEMM + layer-0 transform
    in_gemm<<<(N + 31) / 32, 256, 0, s2>>>(x, W_in, b_in, N);
    conv_gemm<<<(N + 63) / 64, 256, 0, s2>>>(W_conv, N);
    cudaEventRecord(e1, s2);

    // branch A: CSR build + dinv (rows padded to multiple of 8; pads stay zero)
    void* cnt_ptr = nullptr; void* se_ptr = nullptr;
    cudaGetSymbolAddress(&cnt_ptr, g_cnt);
    cudaGetSymbolAddress(&se_ptr, g_se);
    cudaMemsetAsync(cnt_ptr, 0, (size_t)N * sizeof(int));
    size_t se_bytes = (size_t)E * sizeof(unsigned) + (size_t)N * 8 * sizeof(unsigned);
    if (se_bytes > (size_t)EPADMAX * sizeof(unsigned)) se_bytes = (size_t)EPADMAX * sizeof(unsigned);
    cudaMemsetAsync(se_ptr, 0, se_bytes);
    count_kernel<<<(E + 255) / 256, 256>>>(ei + E, E);
    scanA<<<nblk_scan, 1024>>>(N);
    scanC<<<(N + 255) / 256, 256>>>(N);
    build_kernel<<<(E + 255) / 256, 256>>>(ei, E);

    // join
    cudaStreamWaitEvent(0, e1, 0);

    for (int l = 0; l < 3; l++) {
        if (l > 0) conv_gemm<<<(N + 63) / 64, 256>>>(W_conv + l * H * H, N);
        gather_ln<<<(N + 7) / 8, 256>>>(b_conv + l * H, gamma + l * H, beta + l * H,
                                        W_out, b_out, out, N, l == 2);
    }

    cudaEventDestroy(e0);
    cudaEventDestroy(e1);
    cudaStreamDestroy(s2);
}

// round 10
// speedup vs baseline: 1.1946x; 1.1946x over previous
#include <cuda_runtime.h>
#include <cuda_fp16.h>

#define H 64
#define IN_DIM 16
#define NMAX 50048
#define EPADMAX 1200000

// scratch (allocation-free rule: __device__ globals)
__device__ float    g_dinv[NMAX];
__device__ float    g_h[NMAX * H];
__device__ __half   g_th[NMAX * H];     // t stored fp16 (messages)
__device__ int      g_cnt[NMAX];        // in-degree counts (excl self-loop)
__device__ int      g_rowptr[NMAX + 1];
__device__ int      g_wr[NMAX];         // write cursors for CSR fill
__device__ __align__(16) unsigned g_se[EPADMAX];  // packed {norm:f16 <<16 | src:u16}; rows padded to 8
__device__ int      g_bsum[64];         // scan block sums

// ---------------- CSR build ----------------

__global__ void count_kernel(const int* __restrict__ col, int E) {
    int e = blockIdx.x * blockDim.x + threadIdx.x;
    if (e < E) atomicAdd(&g_cnt[col[e]], 1);
}

// block-level exclusive scan of PADDED counts (1024 elems/block)
__global__ void scanA(int N) {
    __shared__ int s[1024];
    int tid = threadIdx.x;
    int i = blockIdx.x * 1024 + tid;
    int v = (i < N) ? ((g_cnt[i] + 7) & ~7) : 0;
    s[tid] = v;
    __syncthreads();
    for (int o = 1; o < 1024; o <<= 1) {
        int t = (tid >= o) ? s[tid - o] : 0;
        __syncthreads();
        s[tid] += t;
        __syncthreads();
    }
    if (i < N) g_rowptr[i] = s[tid] - v;  // exclusive within block
    if (tid == 1023) g_bsum[blockIdx.x] = s[1023];
}

// finalize rowptr: each 256-block computes its 1024-segment's bsum prefix in-warp
__global__ void scanC(int N) {
    __shared__ int sbase;
    int i = blockIdx.x * 256 + threadIdx.x;
    int seg = (blockIdx.x * 256) >> 10;  // all threads of block share one segment
    if (threadIdx.x < 32) {
        int l = threadIdx.x;
        int v = ((l < seg) ? g_bsum[l] : 0) + ((l + 32 < seg) ? g_bsum[l + 32] : 0);
#pragma unroll
        for (int o = 16; o; o >>= 1) v += __shfl_xor_sync(0xFFFFFFFFu, v, o);
        if (l == 0) sbase = v;
    }
    __syncthreads();
    if (i < N) {
        int rp = g_rowptr[i] + sbase;
        g_rowptr[i] = rp;
        g_wr[i] = rp;
        g_dinv[i] = rsqrtf((float)g_cnt[i] + 1.0f);  // +1 self-loop
        if (i == N - 1) g_rowptr[N] = rp + ((g_cnt[i] + 7) & ~7);
    }
}

__global__ void build_kernel(const int* __restrict__ ei, int E) {
    int e = blockIdx.x * blockDim.x + threadIdx.x;
    if (e >= E) return;
    int r = ei[e], c = ei[E + e];
    int slot = atomicAdd(&g_wr[c], 1);
    __half nh = __float2half_rn(g_dinv[r] * g_dinv[c]);
    g_se[slot] = ((unsigned)__half_as_ushort(nh) << 16) | (unsigned)r;  // src < 65536
}

// ---------------- input GEMM: h = relu(x @ W_in + b_in) ----------------

__global__ void in_gemm(const float* __restrict__ x, const float* __restrict__ Win,
                        const float* __restrict__ bin, int N) {
    __shared__ float sW[IN_DIM * H];
    __shared__ float sx[32][IN_DIM];
    int tid = threadIdx.x;
    for (int i = tid; i < IN_DIM * H; i += 256) sW[i] = Win[i];
    int base = blockIdx.x * 32;
    for (int i = tid; i < 32 * IN_DIM; i += 256) {
        int n = i / IN_DIM, k = i % IN_DIM;
        int node = base + n;
        sx[n][k] = (node < N) ? x[node * IN_DIM + k] : 0.0f;
    }
    __syncthreads();
    int j = tid & 63, sub = tid >> 6;
    float bj = bin[j];
    for (int n = sub; n < 32; n += 4) {
        int node = base + n;
        if (node >= N) break;
        float acc = bj;
#pragma unroll
        for (int k = 0; k < IN_DIM; k++) acc += sx[n][k] * sW[k * H + j];
        g_h[node * H + j] = fmaxf(acc, 0.0f);
    }
}

// ---------------- per-layer transform: t = h @ W via mma.sync (fp16 in, fp32 acc, fp16 out) --------
// block = 256 threads (8 warps), 128 nodes. warp w owns rows w*16..w*16+15, all 64 cols.
// shared: sH[m][k] fp16 (stride 72, conflict-free ldmatrix), sWT[n][k] fp16 (W transposed).

#define SHS 72  // padded row stride in halves

__global__ void __launch_bounds__(256) conv_mma(const float* __restrict__ W, int N) {
    __shared__ __half sH[128 * SHS];
    __shared__ __half sWT[64 * SHS];
    int tid = threadIdx.x;
    int base = blockIdx.x * 128;

    // W[k][n] fp32 -> sWT[n][k] fp16
    for (int i = tid; i < 64 * 64; i += 256) {
        int k = i >> 6, n = i & 63;
        sWT[n * SHS + k] = __float2half_rn(W[i]);
    }
    // h fp32 -> sH fp16 (zero-pad OOB rows)
    for (int i = tid; i < 128 * 16; i += 256) {
        int n = i >> 4, q = i & 15;
        int node = base + n;
        float4 v = (node < N) ? *(const float4*)&g_h[node * H + q * 4]
                              : make_float4(0.f, 0.f, 0.f, 0.f);
        __half* dst = &sH[n * SHS + q * 4];
        dst[0] = __float2half_rn(v.x); dst[1] = __float2half_rn(v.y);
        dst[2] = __float2half_rn(v.z); dst[3] = __float2half_rn(v.w);
    }
    __syncthreads();

    int w = tid >> 5, lane = tid & 31;
    int m0 = w * 16;

    float acc[8][4];
#pragma unroll
    for (int nt = 0; nt < 8; nt++)
#pragma unroll
        for (int q = 0; q < 4; q++) acc[nt][q] = 0.0f;

    // A address: lanes 0-15 -> rows m0+0..15 at col kk; lanes 16-31 -> same rows at col kk+8
    unsigned a_base = (unsigned)__cvta_generic_to_shared(
        &sH[(m0 + (lane & 15)) * SHS + ((lane >> 4) & 1) * 8]);
    // B address: lanes 0-7 -> cols n0..n0+7 at k kk; lanes 8-15 -> same at kk+8
    unsigned b_row = lane & 7;
    unsigned b_koff = ((lane >> 3) & 1) * 8;

#pragma unroll
    for (int kk = 0; kk < 64; kk += 16) {
        unsigned a0, a1, a2, a3;
        asm volatile("ldmatrix.sync.aligned.m8n8.x4.shared.b16 {%0,%1,%2,%3}, [%4];"
                     : "=r"(a0), "=r"(a1), "=r"(a2), "=r"(a3)
                     : "r"(a_base + kk * 2));
#pragma unroll
        for (int nt = 0; nt < 8; nt++) {
            unsigned b_addr = (unsigned)__cvta_generic_to_shared(
                &sWT[(nt * 8 + b_row) * SHS + kk + b_koff]);
            unsigned b0, b1;
            asm volatile("ldmatrix.sync.aligned.m8n8.x2.shared.b16 {%0,%1}, [%2];"
                         : "=r"(b0), "=r"(b1) : "r"(b_addr));
            asm volatile("mma.sync.aligned.m16n8k16.row.col.f32.f16.f16.f32 "
                         "{%0,%1,%2,%3}, {%4,%5,%6,%7}, {%8,%9}, {%0,%1,%2,%3};"
                         : "+f"(acc[nt][0]), "+f"(acc[nt][1]), "+f"(acc[nt][2]), "+f"(acc[nt][3])
                         : "r"(a0), "r"(a1), "r"(a2), "r"(a3), "r"(b0), "r"(b1));
        }
    }

    // epilogue: D lane map: c0,c1 -> row l>>2, cols (l&3)*2,+1; c2,c3 -> row+8
    int r0 = base + m0 + (lane >> 2);
    int r1 = r0 + 8;
#pragma unroll
    for (int nt = 0; nt < 8; nt++) {
        int c = nt * 8 + (lane & 3) * 2;
        __half2 p01 = __floats2half2_rn(acc[nt][0], acc[nt][1]);
        __half2 p23 = __floats2half2_rn(acc[nt][2], acc[nt][3]);
        if (r0 < N) *(__half2*)&g_th[r0 * H + c] = p01;
        if (r1 < N) *(__half2*)&g_th[r1 * H + c] = p23;
    }
}

// ---------------- fused gather + bias + self-loop + LN + ReLU + residual (+ head) ----------------
// one warp per node; lane owns features (2*lane, 2*lane+1); messages read as half2.
// rows padded to multiple of 8 (zero-norm sentinels) -> pure unroll-8, no tail.

__device__ __forceinline__ void unpack_se(unsigned m, int& src, float& nm) {
    src = (int)(m & 0xFFFFu);
    nm = __half2float(__ushort_as_half((unsigned short)(m >> 16)));
}

__global__ void gather_ln(const float* __restrict__ b,
                          const float* __restrict__ gamma, const float* __restrict__ beta,
                          const float* __restrict__ Wout, const float* __restrict__ bout,
                          float* __restrict__ out, int N, int last) {
    int node = (blockIdx.x * blockDim.x + threadIdx.x) >> 5;
    int lane = threadIdx.x & 31;
    if (node >= N) return;

    const __half2* t2 = (const __half2*)g_th;
    float d = g_dinv[node];
    float2 b2 = ((const float2*)b)[lane];
    float2 tn = __half22float2(t2[node * 32 + lane]);
    float accx = b2.x + tn.x * d * d;   // bias + self-loop message
    float accy = b2.y + tn.y * d * d;

    int s = g_rowptr[node], e = g_rowptr[node + 1];
    for (int j = s; j < e; j += 8) {
        const uint4* mp = (const uint4*)&g_se[j];
        uint4 ma = mp[0], mb = mp[1];
        int r0, r1, r2, r3, r4, r5, r6, r7;
        float n0, n1, n2, n3, n4, n5, n6, n7;
        unpack_se(ma.x, r0, n0); unpack_se(ma.y, r1, n1);
        unpack_se(ma.z, r2, n2); unpack_se(ma.w, r3, n3);
        unpack_se(mb.x, r4, n4); unpack_se(mb.y, r5, n5);
        unpack_se(mb.z, r6, n6); unpack_se(mb.w, r7, n7);
        float2 v0 = __half22float2(t2[r0 * 32 + lane]);
        float2 v1 = __half22float2(t2[r1 * 32 + lane]);
        float2 v2 = __half22float2(t2[r2 * 32 + lane]);
        float2 v3 = __half22float2(t2[r3 * 32 + lane]);
        float2 v4 = __half22float2(t2[r4 * 32 + lane]);
        float2 v5 = __half22float2(t2[r5 * 32 + lane]);
        float2 v6 = __half22float2(t2[r6 * 32 + lane]);
        float2 v7 = __half22float2(t2[r7 * 32 + lane]);
        accx += v0.x * n0 + v1.x * n1 + v2.x * n2 + v3.x * n3
              + v4.x * n4 + v5.x * n5 + v6.x * n6 + v7.x * n7;
        accy += v0.y * n0 + v1.y * n1 + v2.y * n2 + v3.y * n3
              + v4.y * n4 + v5.y * n5 + v6.y * n6 + v7.y * n7;
    }

    // layernorm over 64 features
    float ssum = accx + accy;
#pragma unroll
    for (int o = 16; o; o >>= 1) ssum += __shfl_xor_sync(0xFFFFFFFFu, ssum, o);
    float mu = ssum * (1.0f / 64.0f);
    float dx = accx - mu, dy = accy - mu;
    float var = dx * dx + dy * dy;
#pragma unroll
    for (int o = 16; o; o >>= 1) var += __shfl_xor_sync(0xFFFFFFFFu, var, o);
    float inv = rsqrtf(var * (1.0f / 64.0f) + 1e-5f);

    float2 g2 = ((const float2*)gamma)[lane];
    float2 be2 = ((const float2*)beta)[lane];
    float2* hp = (float2*)&g_h[node * H];
    float2 hres = hp[lane];
    float r0 = fmaxf(dx * inv * g2.x + be2.x, 0.0f) + hres.x;
    float r1 = fmaxf(dy * inv * g2.y + be2.y, 0.0f) + hres.y;
    hp[lane] = make_float2(r0, r1);

    if (last) {
        float2 w2 = ((const float2*)Wout)[lane];
        float o_ = r0 * w2.x + r1 * w2.y;
#pragma unroll
        for (int o = 16; o; o >>= 1) o_ += __shfl_xor_sync(0xFFFFFFFFu, o_, o);
        if (lane == 0) out[node] = o_ + bout[0];
    }
}

// ---------------- launch ----------------

extern "C" void kernel_launch(void* const* d_in, const int* in_sizes, int n_in,
                              void* d_out, int out_size) {
    const float* x      = (const float*)d_in[0];
    const int*   ei     = (const int*)d_in[1];
    const float* W_in   = (const float*)d_in[2];
    const float* b_in   = (const float*)d_in[3];
    const float* W_conv = (const float*)d_in[4];
    const float* b_conv = (const float*)d_in[5];
    const float* gamma  = (const float*)d_in[6];
    const float* beta   = (const float*)d_in[7];
    const float* W_out  = (const float*)d_in[8];
    const float* b_out  = (const float*)d_in[9];
    float* out = (float*)d_out;

    int N = in_sizes[0] / IN_DIM;
    int E = in_sizes[1] / 2;
    int nblk_scan = (N + 1023) / 1024;

    cudaStream_t s2;
    cudaStreamCreate(&s2);
    cudaEvent_t e0, e1;
    cudaEventCreate(&e0);
    cudaEventCreate(&e1);

    // branch A part 1: CSR counts
    void* cnt_ptr = nullptr; void* se_ptr = nullptr;
    cudaGetSymbolAddress(&cnt_ptr, g_cnt);
    cudaGetSymbolAddress(&se_ptr, g_se);
    cudaMemsetAsync(cnt_ptr, 0, (size_t)N * sizeof(int));
    size_t se_bytes = (size_t)E * sizeof(unsigned) + (size_t)N * 8 * sizeof(unsigned);
    if (se_bytes > (size_t)EPADMAX * sizeof(unsigned)) se_bytes = (size_t)EPADMAX * sizeof(unsigned);
    cudaMemsetAsync(se_ptr, 0, se_bytes);
    count_kernel<<<(E + 255) / 256, 256>>>(ei + E, E);      // kernel 1
    scanA<<<nblk_scan, 1024>>>(N);                          // kernel 2

    // fork branch B (independent): input GEMM + layer-0 transform
    cudaEventRecord(e0, 0);
    cudaStreamWaitEvent(s2, e0, 0);
    in_gemm<<<(N + 31) / 32, 256, 0, s2>>>(x, W_in, b_in, N);   // kernel 3
    conv_mma<<<(N + 127) / 128, 256, 0, s2>>>(W_conv, N);       // kernel 4 (profiled)
    cudaEventRecord(e1, s2);

    // branch A part 2
    scanC<<<(N + 255) / 256, 256>>>(N);
    build_kernel<<<(E + 255) / 256, 256>>>(ei, E);

    // join
    cudaStreamWaitEvent(0, e1, 0);

    for (int l = 0; l < 3; l++) {
        if (l > 0) conv_mma<<<(N + 127) / 128, 256>>>(W_conv + l * H * H, N);
        gather_ln<<<(N + 7) / 8, 256>>>(b_conv + l * H, gamma + l * H, beta + l * H,
                                        W_out, b_out, out, N, l == 2);
    }

    cudaEventDestroy(e0);
    cudaEventDestroy(e1);
    cudaStreamDestroy(s2);
}

// round 11
// speedup vs baseline: 1.2611x; 1.0557x over previous
#include <cuda_runtime.h>
#include <cuda_fp16.h>

#define H 64
#define IN_DIM 16
#define NMAX 50048
#define EPADMAX 1200000

// scratch (allocation-free rule: __device__ globals)
__device__ float    g_dinv[NMAX];
__device__ float    g_h[NMAX * H];
__device__ __half   g_th[NMAX * H];     // t stored fp16 (messages)
__device__ __half   g_wh[3 * H * H];    // W_conv transposed, fp16: [l][n][k]
__device__ int      g_cnt[NMAX];        // in-degree counts (excl self-loop)
__device__ int      g_rowptr[NMAX + 1];
__device__ int      g_wr[NMAX];         // write cursors for CSR fill
__device__ __align__(16) unsigned g_se[EPADMAX];  // packed {norm:f16 <<16 | src:u16}; rows padded to 8
__device__ int      g_bsum[64];         // scan block sums

// ---------------- W pre-convert: g_wh[l][n][k] = fp16(W[l][k][n]) ----------------

__global__ void convW(const float* __restrict__ W) {
    int i = blockIdx.x * blockDim.x + threadIdx.x;  // 3*64*64 = 12288
    if (i >= 3 * H * H) return;
    int l = i >> 12, rem = i & 4095, n = rem >> 6, k = rem & 63;
    g_wh[i] = __float2half_rn(W[l * H * H + k * H + n]);
}

// ---------------- CSR build ----------------

__global__ void count_kernel(const int* __restrict__ col, int E) {
    int e = blockIdx.x * blockDim.x + threadIdx.x;
    if (e < E) atomicAdd(&g_cnt[col[e]], 1);
}

// block-level exclusive scan of PADDED counts (1024 elems/block, shuffle-based)
__global__ void scanA(int N) {
    __shared__ int wsum[32];
    __shared__ int wpre[32];
    int tid = threadIdx.x, lane = tid & 31, w = tid >> 5;
    int i = blockIdx.x * 1024 + tid;
    int v = (i < N) ? ((g_cnt[i] + 7) & ~7) : 0;
    int x = v;
#pragma unroll
    for (int o = 1; o < 32; o <<= 1) {
        int t = __shfl_up_sync(0xFFFFFFFFu, x, o);
        if (lane >= o) x += t;
    }
    if (lane == 31) wsum[w] = x;
    __syncthreads();
    if (w == 0) {
        int y = wsum[lane];
#pragma unroll
        for (int o = 1; o < 32; o <<= 1) {
            int t = __shfl_up_sync(0xFFFFFFFFu, y, o);
            if (lane >= o) y += t;
        }
        wpre[lane] = y - wsum[lane];  // exclusive warp prefix
        if (lane == 31) g_bsum[blockIdx.x] = y;
    }
    __syncthreads();
    if (i < N) g_rowptr[i] = wpre[w] + x - v;  // exclusive within block
}

// finalize rowptr: each 256-block computes its 1024-segment's bsum prefix in-warp
__global__ void scanC(int N) {
    __shared__ int sbase;
    int i = blockIdx.x * 256 + threadIdx.x;
    int seg = (blockIdx.x * 256) >> 10;  // all threads of block share one segment
    if (threadIdx.x < 32) {
        int l = threadIdx.x;
        int v = ((l < seg) ? g_bsum[l] : 0) + ((l + 32 < seg) ? g_bsum[l + 32] : 0);
#pragma unroll
        for (int o = 16; o; o >>= 1) v += __shfl_xor_sync(0xFFFFFFFFu, v, o);
        if (l == 0) sbase = v;
    }
    __syncthreads();
    if (i < N) {
        int rp = g_rowptr[i] + sbase;
        g_rowptr[i] = rp;
        g_wr[i] = rp;
        g_dinv[i] = rsqrtf((float)g_cnt[i] + 1.0f);  // +1 self-loop
        if (i == N - 1) g_rowptr[N] = rp + ((g_cnt[i] + 7) & ~7);
    }
}

__global__ void build_kernel(const int* __restrict__ ei, int E) {
    int e = blockIdx.x * blockDim.x + threadIdx.x;
    if (e >= E) return;
    int r = ei[e], c = ei[E + e];
    int slot = atomicAdd(&g_wr[c], 1);
    __half nh = __float2half_rn(g_dinv[r] * g_dinv[c]);
    g_se[slot] = ((unsigned)__half_as_ushort(nh) << 16) | (unsigned)r;  // src < 65536
}

// ---------------- input GEMM: h = relu(x @ W_in + b_in) ----------------

__global__ void in_gemm(const float* __restrict__ x, const float* __restrict__ Win,
                        const float* __restrict__ bin, int N) {
    __shared__ float sW[IN_DIM * H];
    __shared__ float sx[32][IN_DIM];
    int tid = threadIdx.x;
    for (int i = tid; i < IN_DIM * H; i += 256) sW[i] = Win[i];
    int base = blockIdx.x * 32;
    for (int i = tid; i < 32 * IN_DIM; i += 256) {
        int n = i / IN_DIM, k = i % IN_DIM;
        int node = base + n;
        sx[n][k] = (node < N) ? x[node * IN_DIM + k] : 0.0f;
    }
    __syncthreads();
    int j = tid & 63, sub = tid >> 6;
    float bj = bin[j];
    for (int n = sub; n < 32; n += 4) {
        int node = base + n;
        if (node >= N) break;
        float acc = bj;
#pragma unroll
        for (int k = 0; k < IN_DIM; k++) acc += sx[n][k] * sW[k * H + j];
        g_h[node * H + j] = fmaxf(acc, 0.0f);
    }
}

// ---------------- per-layer transform: t = h @ W via mma.sync (fp16 in, fp32 acc, fp16 out) --------
// block = 256 threads (8 warps), 128 nodes. warp w owns rows w*16..w*16+15, all 64 cols.
// W read pre-converted fp16 from g_wh; B fragments loaded as ldmatrix.x4 (2 n-tiles per load).

#define SHS 72  // padded row stride in halves (144 B, 16B-aligned rows)

__global__ void __launch_bounds__(256) conv_mma(int layer, int N) {
    __shared__ __half sH[128 * SHS];
    __shared__ __half sWT[64 * SHS];
    int tid = threadIdx.x;
    int base = blockIdx.x * 128;

    // fp16 W tile copy: 64 rows x 64 halves, uint4 chunks (8 halves)
    {
        const uint4* wsrc = (const uint4*)&g_wh[layer * H * H];
        for (int i = tid; i < 512; i += 256) {
            int row = i >> 3, q = i & 7;
            *(uint4*)&sWT[row * SHS + q * 8] = wsrc[row * 8 + q];
        }
    }
    // h fp32 -> sH fp16 (zero-pad OOB rows)
    for (int i = tid; i < 128 * 16; i += 256) {
        int n = i >> 4, q = i & 15;
        int node = base + n;
        float4 v = (node < N) ? *(const float4*)&g_h[node * H + q * 4]
                              : make_float4(0.f, 0.f, 0.f, 0.f);
        __half2* dst = (__half2*)&sH[n * SHS + q * 4];
        dst[0] = __floats2half2_rn(v.x, v.y);
        dst[1] = __floats2half2_rn(v.z, v.w);
    }
    __syncthreads();

    int w = tid >> 5, lane = tid & 31;
    int m0 = w * 16;

    float acc[8][4];
#pragma unroll
    for (int nt = 0; nt < 8; nt++)
#pragma unroll
        for (int q = 0; q < 4; q++) acc[nt][q] = 0.0f;

    // A: lanes 0-15 -> rows m0+0..15 at col kk; lanes 16-31 -> same rows at col kk+8
    unsigned a_base = (unsigned)__cvta_generic_to_shared(
        &sH[(m0 + (lane & 15)) * SHS + ((lane >> 4) & 1) * 8]);
    // B x4: matrix m = lane>>3 (0..3), row = lane&7
    //   group g covers n-tiles 2g, 2g+1: m0=(t2g,k0) m1=(t2g,k8) m2=(t2g+1,k0) m3=(t2g+1,k8)
    int bm = lane >> 3, brow = lane & 7;

#pragma unroll
    for (int kk = 0; kk < 64; kk += 16) {
        unsigned a0, a1, a2, a3;
        asm volatile("ldmatrix.sync.aligned.m8n8.x4.shared.b16 {%0,%1,%2,%3}, [%4];"
                     : "=r"(a0), "=r"(a1), "=r"(a2), "=r"(a3)
                     : "r"(a_base + kk * 2));
#pragma unroll
        for (int g = 0; g < 4; g++) {
            unsigned b_addr = (unsigned)__cvta_generic_to_shared(
                &sWT[((2 * g + (bm >> 1)) * 8 + brow) * SHS + kk + (bm & 1) * 8]);
            unsigned b0, b1, b2, b3;
            asm volatile("ldmatrix.sync.aligned.m8n8.x4.shared.b16 {%0,%1,%2,%3}, [%4];"
                         : "=r"(b0), "=r"(b1), "=r"(b2), "=r"(b3) : "r"(b_addr));
            int t0 = 2 * g, t1 = 2 * g + 1;
            asm volatile("mma.sync.aligned.m16n8k16.row.col.f32.f16.f16.f32 "
                         "{%0,%1,%2,%3}, {%4,%5,%6,%7}, {%8,%9}, {%0,%1,%2,%3};"
                         : "+f"(acc[t0][0]), "+f"(acc[t0][1]), "+f"(acc[t0][2]), "+f"(acc[t0][3])
                         : "r"(a0), "r"(a1), "r"(a2), "r"(a3), "r"(b0), "r"(b1));
            asm volatile("mma.sync.aligned.m16n8k16.row.col.f32.f16.f16.f32 "
                         "{%0,%1,%2,%3}, {%4,%5,%6,%7}, {%8,%9}, {%0,%1,%2,%3};"
                         : "+f"(acc[t1][0]), "+f"(acc[t1][1]), "+f"(acc[t1][2]), "+f"(acc[t1][3])
                         : "r"(a0), "r"(a1), "r"(a2), "r"(a3), "r"(b2), "r"(b3));
        }
    }

    // epilogue: c0,c1 -> row lane>>2, cols (lane&3)*2,+1; c2,c3 -> row+8
    int r0 = base + m0 + (lane >> 2);
    int r1 = r0 + 8;
#pragma unroll
    for (int nt = 0; nt < 8; nt++) {
        int c = nt * 8 + (lane & 3) * 2;
        __half2 p01 = __floats2half2_rn(acc[nt][0], acc[nt][1]);
        __half2 p23 = __floats2half2_rn(acc[nt][2], acc[nt][3]);
        if (r0 < N) *(__half2*)&g_th[r0 * H + c] = p01;
        if (r1 < N) *(__half2*)&g_th[r1 * H + c] = p23;
    }
}

// ---------------- fused gather + bias + self-loop + LN + ReLU + residual (+ head) ----------------
// one warp per node; lane owns features (2*lane, 2*lane+1); messages read as half2.
// rows padded to multiple of 8 (zero-norm sentinels) -> pure unroll-8, no tail.

__device__ __forceinline__ void unpack_se(unsigned m, int& src, float& nm) {
    src = (int)(m & 0xFFFFu);
    nm = __half2float(__ushort_as_half((unsigned short)(m >> 16)));
}

__global__ void gather_ln(const float* __restrict__ b,
                          const float* __restrict__ gamma, const float* __restrict__ beta,
                          const float* __restrict__ Wout, const float* __restrict__ bout,
                          float* __restrict__ out, int N, int last) {
    int node = (blockIdx.x * blockDim.x + threadIdx.x) >> 5;
    int lane = threadIdx.x & 31;
    if (node >= N) return;

    const __half2* t2 = (const __half2*)g_th;
    float d = g_dinv[node];
    float2 b2 = ((const float2*)b)[lane];
    float2 tn = __half22float2(t2[node * 32 + lane]);
    float accx = b2.x + tn.x * d * d;   // bias + self-loop message
    float accy = b2.y + tn.y * d * d;

    int s = g_rowptr[node], e = g_rowptr[node + 1];
    for (int j = s; j < e; j += 8) {
        const uint4* mp = (const uint4*)&g_se[j];
        uint4 ma = mp[0], mb = mp[1];
        int r0, r1, r2, r3, r4, r5, r6, r7;
        float n0, n1, n2, n3, n4, n5, n6, n7;
        unpack_se(ma.x, r0, n0); unpack_se(ma.y, r1, n1);
        unpack_se(ma.z, r2, n2); unpack_se(ma.w, r3, n3);
        unpack_se(mb.x, r4, n4); unpack_se(mb.y, r5, n5);
        unpack_se(mb.z, r6, n6); unpack_se(mb.w, r7, n7);
        float2 v0 = __half22float2(t2[r0 * 32 + lane]);
        float2 v1 = __half22float2(t2[r1 * 32 + lane]);
        float2 v2 = __half22float2(t2[r2 * 32 + lane]);
        float2 v3 = __half22float2(t2[r3 * 32 + lane]);
        float2 v4 = __half22float2(t2[r4 * 32 + lane]);
        float2 v5 = __half22float2(t2[r5 * 32 + lane]);
        float2 v6 = __half22float2(t2[r6 * 32 + lane]);
        float2 v7 = __half22float2(t2[r7 * 32 + lane]);
        accx += v0.x * n0 + v1.x * n1 + v2.x * n2 + v3.x * n3
              + v4.x * n4 + v5.x * n5 + v6.x * n6 + v7.x * n7;
        accy += v0.y * n0 + v1.y * n1 + v2.y * n2 + v3.y * n3
              + v4.y * n4 + v5.y * n5 + v6.y * n6 + v7.y * n7;
    }

    // layernorm over 64 features
    float ssum = accx + accy;
#pragma unroll
    for (int o = 16; o; o >>= 1) ssum += __shfl_xor_sync(0xFFFFFFFFu, ssum, o);
    float mu = ssum * (1.0f / 64.0f);
    float dx = accx - mu, dy = accy - mu;
    float var = dx * dx + dy * dy;
#pragma unroll
    for (int o = 16; o; o >>= 1) var += __shfl_xor_sync(0xFFFFFFFFu, var, o);
    float inv = rsqrtf(var * (1.0f / 64.0f) + 1e-5f);

    float2 g2 = ((const float2*)gamma)[lane];
    float2 be2 = ((const float2*)beta)[lane];
    float2* hp = (float2*)&g_h[node * H];
    float2 hres = hp[lane];
    float r0 = fmaxf(dx * inv * g2.x + be2.x, 0.0f) + hres.x;
    float r1 = fmaxf(dy * inv * g2.y + be2.y, 0.0f) + hres.y;
    hp[lane] = make_float2(r0, r1);

    if (last) {
        float2 w2 = ((const float2*)Wout)[lane];
        float o_ = r0 * w2.x + r1 * w2.y;
#pragma unroll
        for (int o = 16; o; o >>= 1) o_ += __shfl_xor_sync(0xFFFFFFFFu, o_, o);
        if (lane == 0) out[node] = o_ + bout[0];
    }
}

// ---------------- launch ----------------

extern "C" void kernel_launch(void* const* d_in, const int* in_sizes, int n_in,
                              void* d_out, int out_size) {
    const float* x      = (const float*)d_in[0];
    const int*   ei     = (const int*)d_in[1];
    const float* W_in   = (const float*)d_in[2];
    const float* b_in   = (const float*)d_in[3];
    const float* W_conv = (const float*)d_in[4];
    const float* b_conv = (const float*)d_in[5];
    const float* gamma  = (const float*)d_in[6];
    const float* beta   = (const float*)d_in[7];
    const float* W_out  = (const float*)d_in[8];
    const float* b_out  = (const float*)d_in[9];
    float* out = (float*)d_out;

    int N = in_sizes[0] / IN_DIM;
    int E = in_sizes[1] / 2;
    int nblk_scan = (N + 1023) / 1024;

    cudaStream_t s2;
    cudaStreamCreate(&s2);
    cudaEvent_t e0, e1;
    cudaEventCreate(&e0);
    cudaEventCreate(&e1);

    // branch A part 1: CSR counts
    void* cnt_ptr = nullptr; void* se_ptr = nullptr;
    cudaGetSymbolAddress(&cnt_ptr, g_cnt);
    cudaGetSymbolAddress(&se_ptr, g_se);
    cudaMemsetAsync(cnt_ptr, 0, (size_t)N * sizeof(int));
    size_t se_bytes = (size_t)E * sizeof(unsigned) + (size_t)N * 8 * sizeof(unsigned);
    if (se_bytes > (size_t)EPADMAX * sizeof(unsigned)) se_bytes = (size_t)EPADMAX * sizeof(unsigned);
    cudaMemsetAsync(se_ptr, 0, se_bytes);
    count_kernel<<<(E + 255) / 256, 256>>>(ei + E, E);
    scanA<<<nblk_scan, 1024>>>(N);

    // fork branch B (independent): W convert + input GEMM + layer-0 transform
    cudaEventRecord(e0, 0);
    cudaStreamWaitEvent(s2, e0, 0);
    convW<<<48, 256, 0, s2>>>(W_conv);
    in_gemm<<<(N + 31) / 32, 256, 0, s2>>>(x, W_in, b_in, N);
    conv_mma<<<(N + 127) / 128, 256, 0, s2>>>(0, N);
    cudaEventRecord(e1, s2);

    // branch A part 2
    scanC<<<(N + 255) / 256, 256>>>(N);
    build_kernel<<<(E + 255) / 256, 256>>>(ei, E);

    // join
    cudaStreamWaitEvent(0, e1, 0);

    for (int l = 0; l < 3; l++) {
        if (l > 0) conv_mma<<<(N + 127) / 128, 256>>>(l, N);
        gather_ln<<<(N + 7) / 8, 256>>>(b_conv + l * H, gamma + l * H, beta + l * H,
                                        W_out, b_out, out, N, l == 2);
    }

    cudaEventDestroy(e0);
    cudaEventDestroy(e1);
    cudaStreamDestroy(s2);
}

// round 12
// speedup vs baseline: 1.3217x; 1.0480x over previous
#include <cuda_runtime.h>
#include <cuda_fp16.h>

#define H 64
#define IN_DIM 16
#define NMAX 50048
#define EPADMAX 1200000

// scratch (allocation-free rule: __device__ globals)
__device__ float    g_dinv[NMAX];
__device__ float    g_h[NMAX * H];
__device__ __half   g_th[NMAX * H];     // t stored fp16 (messages)
__device__ __half   g_wh[3 * H * H];    // W_conv transposed, fp16: [l][n][k]
__device__ int      g_cnt[NMAX];        // in-degree counts (excl self-loop)
__device__ int      g_rowptr[NMAX + 1];
__device__ int      g_wr[NMAX];         // write cursors for CSR fill
__device__ __align__(16) unsigned g_se[EPADMAX];  // packed {norm:f16 <<16 | src:u16}; rows padded to 8
__device__ int      g_bsum[64];         // scan block sums

// ---------------- W pre-convert: g_wh[l][n][k] = fp16(W[l][k][n]) ----------------

__global__ void convW(const float* __restrict__ W) {
    int i = blockIdx.x * blockDim.x + threadIdx.x;  // 3*64*64 = 12288
    if (i >= 3 * H * H) return;
    int l = i >> 12, rem = i & 4095, n = rem >> 6, k = rem & 63;
    g_wh[i] = __float2half_rn(W[l * H * H + k * H + n]);
}

// ---------------- CSR build ----------------

__global__ void count_kernel(const int* __restrict__ col, int E) {
    int e = blockIdx.x * blockDim.x + threadIdx.x;
    if (e < E) atomicAdd(&g_cnt[col[e]], 1);
}

// block-level exclusive scan of PADDED counts (1024 elems/block, shuffle-based)
__global__ void scanA(int N) {
    __shared__ int wsum[32];
    __shared__ int wpre[32];
    int tid = threadIdx.x, lane = tid & 31, w = tid >> 5;
    int i = blockIdx.x * 1024 + tid;
    int v = (i < N) ? ((g_cnt[i] + 7) & ~7) : 0;
    int x = v;
#pragma unroll
    for (int o = 1; o < 32; o <<= 1) {
        int t = __shfl_up_sync(0xFFFFFFFFu, x, o);
        if (lane >= o) x += t;
    }
    if (lane == 31) wsum[w] = x;
    __syncthreads();
    if (w == 0) {
        int y = wsum[lane];
#pragma unroll
        for (int o = 1; o < 32; o <<= 1) {
            int t = __shfl_up_sync(0xFFFFFFFFu, y, o);
            if (lane >= o) y += t;
        }
        wpre[lane] = y - wsum[lane];  // exclusive warp prefix
        if (lane == 31) g_bsum[blockIdx.x] = y;
    }
    __syncthreads();
    if (i < N) g_rowptr[i] = wpre[w] + x - v;  // exclusive within block
}

// finalize rowptr: each 256-block computes its 1024-segment's bsum prefix in-warp
__global__ void scanC(int N) {
    __shared__ int sbase;
    int i = blockIdx.x * 256 + threadIdx.x;
    int seg = (blockIdx.x * 256) >> 10;  // all threads of block share one segment
    if (threadIdx.x < 32) {
        int l = threadIdx.x;
        int v = ((l < seg) ? g_bsum[l] : 0) + ((l + 32 < seg) ? g_bsum[l + 32] : 0);
#pragma unroll
        for (int o = 16; o; o >>= 1) v += __shfl_xor_sync(0xFFFFFFFFu, v, o);
        if (l == 0) sbase = v;
    }
    __syncthreads();
    if (i < N) {
        int rp = g_rowptr[i] + sbase;
        g_rowptr[i] = rp;
        g_wr[i] = rp;
        g_dinv[i] = rsqrtf((float)g_cnt[i] + 1.0f);  // +1 self-loop
        if (i == N - 1) g_rowptr[N] = rp + ((g_cnt[i] + 7) & ~7);
    }
}

__global__ void build_kernel(const int* __restrict__ ei, int E) {
    int e = blockIdx.x * blockDim.x + threadIdx.x;
    if (e >= E) return;
    int r = ei[e], c = ei[E + e];
    int slot = atomicAdd(&g_wr[c], 1);
    __half nh = __float2half_rn(g_dinv[r] * g_dinv[c]);
    g_se[slot] = ((unsigned)__half_as_ushort(nh) << 16) | (unsigned)r;  // src < 65536
}

// ---------------- input GEMM: h = relu(x @ W_in + b_in) ----------------
// 64 nodes/block, 256 threads = 64 cols x 4 subsets (16 nodes each).
// W column held in 16 registers; sx read as float4 (broadcast, conflict-free).

__global__ void __launch_bounds__(256) in_gemm(const float* __restrict__ x,
                                               const float* __restrict__ Win,
                                               const float* __restrict__ bin, int N) {
    __shared__ __align__(16) float sx[64][IN_DIM];  // 4 KB
    int tid = threadIdx.x;
    int j = tid & 63, sub = tid >> 6;
    int base = blockIdx.x * 64;
    int nn = N - base;
    if (nn > 64) nn = 64;
    if (nn <= 0) return;

    // W column -> registers (coalesced across j)
    float w[IN_DIM];
#pragma unroll
    for (int k = 0; k < IN_DIM; k++) w[k] = Win[k * H + j];
    float bj = bin[j];

    // x tile -> shared via float4 (64 nodes x 16 floats = 256 float4)
    const float4* xsrc = (const float4*)&x[base * IN_DIM];
    float4* sdst = (float4*)sx;
    int nvec = nn * (IN_DIM / 4);
    for (int i = tid; i < nvec; i += 256) sdst[i] = xsrc[i];
    __syncthreads();

    for (int n = sub; n < nn; n += 4) {
        const float4* sp = (const float4*)&sx[n][0];
        float4 s0 = sp[0], s1 = sp[1], s2 = sp[2], s3 = sp[3];
        float acc = bj;
        acc += s0.x * w[0]  + s0.y * w[1]  + s0.z * w[2]  + s0.w * w[3];
        acc += s1.x * w[4]  + s1.y * w[5]  + s1.z * w[6]  + s1.w * w[7];
        acc += s2.x * w[8]  + s2.y * w[9]  + s2.z * w[10] + s2.w * w[11];
        acc += s3.x * w[12] + s3.y * w[13] + s3.z * w[14] + s3.w * w[15];
        g_h[(base + n) * H + j] = fmaxf(acc, 0.0f);
    }
}

// ---------------- per-layer transform: t = h @ W via mma.sync (fp16 in, fp32 acc, fp16 out) --------

#define SHS 72  // padded row stride in halves (144 B, 16B-aligned rows)

__global__ void __launch_bounds__(256) conv_mma(int layer, int N) {
    __shared__ __half sH[128 * SHS];
    __shared__ __half sWT[64 * SHS];
    int tid = threadIdx.x;
    int base = blockIdx.x * 128;

    // fp16 W tile copy: 64 rows x 64 halves, uint4 chunks (8 halves)
    {
        const uint4* wsrc = (const uint4*)&g_wh[layer * H * H];
        for (int i = tid; i < 512; i += 256) {
            int row = i >> 3, q = i & 7;
            *(uint4*)&sWT[row * SHS + q * 8] = wsrc[row * 8 + q];
        }
    }
    // h fp32 -> sH fp16 (zero-pad OOB rows)
    for (int i = tid; i < 128 * 16; i += 256) {
        int n = i >> 4, q = i & 15;
        int node = base + n;
        float4 v = (node < N) ? *(const float4*)&g_h[node * H + q * 4]
                              : make_float4(0.f, 0.f, 0.f, 0.f);
        __half2* dst = (__half2*)&sH[n * SHS + q * 4];
        dst[0] = __floats2half2_rn(v.x, v.y);
        dst[1] = __floats2half2_rn(v.z, v.w);
    }
    __syncthreads();

    int w = tid >> 5, lane = tid & 31;
    int m0 = w * 16;

    float acc[8][4];
#pragma unroll
    for (int nt = 0; nt < 8; nt++)
#pragma unroll
        for (int q = 0; q < 4; q++) acc[nt][q] = 0.0f;

    unsigned a_base = (unsigned)__cvta_generic_to_shared(
        &sH[(m0 + (lane & 15)) * SHS + ((lane >> 4) & 1) * 8]);
    int bm = lane >> 3, brow = lane & 7;

#pragma unroll
    for (int kk = 0; kk < 64; kk += 16) {
        unsigned a0, a1, a2, a3;
        asm volatile("ldmatrix.sync.aligned.m8n8.x4.shared.b16 {%0,%1,%2,%3}, [%4];"
                     : "=r"(a0), "=r"(a1), "=r"(a2), "=r"(a3)
                     : "r"(a_base + kk * 2));
#pragma unroll
        for (int g = 0; g < 4; g++) {
            unsigned b_addr = (unsigned)__cvta_generic_to_shared(
                &sWT[((2 * g + (bm >> 1)) * 8 + brow) * SHS + kk + (bm & 1) * 8]);
            unsigned b0, b1, b2, b3;
            asm volatile("ldmatrix.sync.aligned.m8n8.x4.shared.b16 {%0,%1,%2,%3}, [%4];"
                         : "=r"(b0), "=r"(b1), "=r"(b2), "=r"(b3) : "r"(b_addr));
            int t0 = 2 * g, t1 = 2 * g + 1;
            asm volatile("mma.sync.aligned.m16n8k16.row.col.f32.f16.f16.f32 "
                         "{%0,%1,%2,%3}, {%4,%5,%6,%7}, {%8,%9}, {%0,%1,%2,%3};"
                         : "+f"(acc[t0][0]), "+f"(acc[t0][1]), "+f"(acc[t0][2]), "+f"(acc[t0][3])
                         : "r"(a0), "r"(a1), "r"(a2), "r"(a3), "r"(b0), "r"(b1));
            asm volatile("mma.sync.aligned.m16n8k16.row.col.f32.f16.f16.f32 "
                         "{%0,%1,%2,%3}, {%4,%5,%6,%7}, {%8,%9}, {%0,%1,%2,%3};"
                         : "+f"(acc[t1][0]), "+f"(acc[t1][1]), "+f"(acc[t1][2]), "+f"(acc[t1][3])
                         : "r"(a0), "r"(a1), "r"(a2), "r"(a3), "r"(b2), "r"(b3));
        }
    }

    int r0 = base + m0 + (lane >> 2);
    int r1 = r0 + 8;
#pragma unroll
    for (int nt = 0; nt < 8; nt++) {
        int c = nt * 8 + (lane & 3) * 2;
        __half2 p01 = __floats2half2_rn(acc[nt][0], acc[nt][1]);
        __half2 p23 = __floats2half2_rn(acc[nt][2], acc[nt][3]);
        if (r0 < N) *(__half2*)&g_th[r0 * H + c] = p01;
        if (r1 < N) *(__half2*)&g_th[r1 * H + c] = p23;
    }
}

// ---------------- fused gather + bias + self-loop + LN + ReLU + residual (+ head) ----------------

__device__ __forceinline__ void unpack_se(unsigned m, int& src, float& nm) {
    src = (int)(m & 0xFFFFu);
    nm = __half2float(__ushort_as_half((unsigned short)(m >> 16)));
}

__global__ void gather_ln(const float* __restrict__ b,
                          const float* __restrict__ gamma, const float* __restrict__ beta,
                          const float* __restrict__ Wout, const float* __restrict__ bout,
                          float* __restrict__ out, int N, int last) {
    int node = (blockIdx.x * blockDim.x + threadIdx.x) >> 5;
    int lane = threadIdx.x & 31;
    if (node >= N) return;

    const __half2* t2 = (const __half2*)g_th;
    float d = g_dinv[node];
    float2 b2 = ((const float2*)b)[lane];
    float2 tn = __half22float2(t2[node * 32 + lane]);
    float accx = b2.x + tn.x * d * d;   // bias + self-loop message
    float accy = b2.y + tn.y * d * d;

    int s = g_rowptr[node], e = g_rowptr[node + 1];
    for (int j = s; j < e; j += 8) {
        const uint4* mp = (const uint4*)&g_se[j];
        uint4 ma = mp[0], mb = mp[1];
        int r0, r1, r2, r3, r4, r5, r6, r7;
        float n0, n1, n2, n3, n4, n5, n6, n7;
        unpack_se(ma.x, r0, n0); unpack_se(ma.y, r1, n1);
        unpack_se(ma.z, r2, n2); unpack_se(ma.w, r3, n3);
        unpack_se(mb.x, r4, n4); unpack_se(mb.y, r5, n5);
        unpack_se(mb.z, r6, n6); unpack_se(mb.w, r7, n7);
        float2 v0 = __half22float2(t2[r0 * 32 + lane]);
        float2 v1 = __half22float2(t2[r1 * 32 + lane]);
        float2 v2 = __half22float2(t2[r2 * 32 + lane]);
        float2 v3 = __half22float2(t2[r3 * 32 + lane]);
        float2 v4 = __half22float2(t2[r4 * 32 + lane]);
        float2 v5 = __half22float2(t2[r5 * 32 + lane]);
        float2 v6 = __half22float2(t2[r6 * 32 + lane]);
        float2 v7 = __half22float2(t2[r7 * 32 + lane]);
        accx += v0.x * n0 + v1.x * n1 + v2.x * n2 + v3.x * n3
              + v4.x * n4 + v5.x * n5 + v6.x * n6 + v7.x * n7;
        accy += v0.y * n0 + v1.y * n1 + v2.y * n2 + v3.y * n3
              + v4.y * n4 + v5.y * n5 + v6.y * n6 + v7.y * n7;
    }

    // layernorm over 64 features
    float ssum = accx + accy;
#pragma unroll
    for (int o = 16; o; o >>= 1) ssum += __shfl_xor_sync(0xFFFFFFFFu, ssum, o);
    float mu = ssum * (1.0f / 64.0f);
    float dx = accx - mu, dy = accy - mu;
    float var = dx * dx + dy * dy;
#pragma unroll
    for (int o = 16; o; o >>= 1) var += __shfl_xor_sync(0xFFFFFFFFu, var, o);
    float inv = rsqrtf(var * (1.0f / 64.0f) + 1e-5f);

    float2 g2 = ((const float2*)gamma)[lane];
    float2 be2 = ((const float2*)beta)[lane];
    float2* hp = (float2*)&g_h[node * H];
    float2 hres = hp[lane];
    float r0 = fmaxf(dx * inv * g2.x + be2.x, 0.0f) + hres.x;
    float r1 = fmaxf(dy * inv * g2.y + be2.y, 0.0f) + hres.y;
    hp[lane] = make_float2(r0, r1);

    if (last) {
        float2 w2 = ((const float2*)Wout)[lane];
        float o_ = r0 * w2.x + r1 * w2.y;
#pragma unroll
        for (int o = 16; o; o >>= 1) o_ += __shfl_xor_sync(0xFFFFFFFFu, o_, o);
        if (lane == 0) out[node] = o_ + bout[0];
    }
}

// ---------------- launch ----------------

extern "C" void kernel_launch(void* const* d_in, const int* in_sizes, int n_in,
                              void* d_out, int out_size) {
    const float* x      = (const float*)d_in[0];
    const int*   ei     = (const int*)d_in[1];
    const float* W_in   = (const float*)d_in[2];
    const float* b_in   = (const float*)d_in[3];
    const float* W_conv = (const float*)d_in[4];
    const float* b_conv = (const float*)d_in[5];
    const float* gamma  = (const float*)d_in[6];
    const float* beta   = (const float*)d_in[7];
    const float* W_out  = (const float*)d_in[8];
    const float* b_out  = (const float*)d_in[9];
    float* out = (float*)d_out;

    int N = in_sizes[0] / IN_DIM;
    int E = in_sizes[1] / 2;
    int nblk_scan = (N + 1023) / 1024;

    cudaStream_t s2;
    cudaStreamCreate(&s2);
    cudaEvent_t e0, e1;
    cudaEventCreate(&e0);
    cudaEventCreate(&e1);

    // branch A part 1: CSR counts
    void* cnt_ptr = nullptr; void* se_ptr = nullptr;
    cudaGetSymbolAddress(&cnt_ptr, g_cnt);
    cudaGetSymbolAddress(&se_ptr, g_se);
    cudaMemsetAsync(cnt_ptr, 0, (size_t)N * sizeof(int));
    size_t se_bytes = (size_t)E * sizeof(unsigned) + (size_t)N * 8 * sizeof(unsigned);
    if (se_bytes > (size_t)EPADMAX * sizeof(unsigned)) se_bytes = (size_t)EPADMAX * sizeof(unsigned);
    cudaMemsetAsync(se_ptr, 0, se_bytes);
    count_kernel<<<(E + 255) / 256, 256>>>(ei + E, E);
    scanA<<<nblk_scan, 1024>>>(N);

    // fork branch B (independent): W convert + input GEMM + layer-0 transform
    cudaEventRecord(e0, 0);
    cudaStreamWaitEvent(s2, e0, 0);
    convW<<<48, 256, 0, s2>>>(W_conv);
    in_gemm<<<(N + 63) / 64, 256, 0, s2>>>(x, W_in, b_in, N);
    conv_mma<<<(N + 127) / 128, 256, 0, s2>>>(0, N);
    cudaEventRecord(e1, s2);

    // branch A part 2
    scanC<<<(N + 255) / 256, 256>>>(N);
    build_kernel<<<(E + 255) / 256, 256>>>(ei, E);

    // join
    cudaStreamWaitEvent(0, e1, 0);

    for (int l = 0; l < 3; l++) {
        if (l > 0) conv_mma<<<(N + 127) / 128, 256>>>(l, N);
        gather_ln<<<(N + 7) / 8, 256>>>(b_conv + l * H, gamma + l * H, beta + l * H,
                                        W_out, b_out, out, N, l == 2);
    }

    cudaEventDestroy(e0);
    cudaEventDestroy(e1);
    cudaStreamDestroy(s2);
}